// round 12
// baseline (speedup 1.0000x reference)
#include <cuda_runtime.h>
#include <math.h>

#define TT     256   // B*S tiles
#define NTOK   256   // N tokens per tile
#define DMODEL 512
#define NH     8
#define HD     64

typedef unsigned long long u64t;

// ---------------- f32x2 packed-math helpers (B300 FFMA2 path) ---------------
__device__ __forceinline__ u64t pack2(float lo, float hi) {
    u64t r; asm("mov.b64 %0, {%1,%2};" : "=l"(r) : "f"(lo), "f"(hi)); return r;
}
__device__ __forceinline__ void fma2(u64t& d, u64t a, u64t b) {
    asm("fma.rn.f32x2 %0, %1, %2, %0;" : "+l"(d) : "l"(a), "l"(b));
}
__device__ __forceinline__ float2 unpack2(u64t v) {
    float2 f; asm("mov.b64 {%0,%1}, %2;" : "=f"(f.x), "=f"(f.y) : "l"(v)); return f;
}

// ---------------- scratch (device globals: no allocation allowed) -----------
__device__ float g_Q[TT * DMODEL];          // q per tile (with bias)
__device__ float g_P[TT * NH * DMODEL];     // [t][h][d], pre-scaled by 1/8
__device__ float g_Y[TT * NH * DMODEL];     // [t][h][d], softmax-weighted x sums
__device__ float g_ctx[TT * DMODEL];        // concat heads per tile

// ------------- register-blocked GEMM: C = A @ B + bias ----------------------
// 32x64 tile, 256 threads, 2x4 micro-tile per thread.
// A staged as DUPLICATED f32x2 pairs -> inner loop: 1 LDS.128 (bcast) +
// 1 LDS.128 + 4 FMA2 per k. Double-buffered k=32 chunks with reg prefetch.
__global__ __launch_bounds__(256) void gemm_k(
    const float* __restrict__ A, size_t a_stride, size_t a_zoff,
    const float* __restrict__ B, int b_stride, int b_zoff,
    const float* __restrict__ bias, int bias_zoff,
    float* __restrict__ C, int c_stride, int c_zoff,
    int Kdim)
{
    __shared__ __align__(16) u64t  Atp[2][32 * 34];  // [kk][row] dup pairs, pad 34
    __shared__ __align__(16) float Bs[2][32 * 64];   // [kk][col]
    int tid = threadIdx.x;
    int tx = tid & 15, ty = tid >> 4;                // tx: col quad, ty: row pair
    int t0 = blockIdx.x * 32;
    int n0 = blockIdx.y * 64;
    int z  = blockIdx.z;

    const float* Ab    = A + (size_t)z * a_zoff;
    const float* Bb    = B + (size_t)z * b_zoff + n0;
    const float* biasb = bias + (size_t)z * bias_zoff + n0;
    float*       Cb    = C + (size_t)z * c_zoff + n0;

    // staging coords: A 32x32 (1 float4/thread), B 32x64 (2 float4/thread)
    int arow = tid >> 3, akq = tid & 7;
    const float* Aptr = Ab + (size_t)(t0 + arow) * a_stride + akq * 4;
    int br0 = tid >> 4, bc0 = (tid & 15) * 4;        // +16 rows for 2nd f4
    const float* Bptr = Bb + (size_t)br0 * b_stride + bc0;

    float4 pa, pb0, pb1;
    pa  = *(const float4*)(Aptr);
    pb0 = *(const float4*)(Bptr);
    pb1 = *(const float4*)(Bptr + (size_t)16 * b_stride);
    {
        Atp[0][(akq * 4 + 0) * 34 + arow] = pack2(pa.x, pa.x);
        Atp[0][(akq * 4 + 1) * 34 + arow] = pack2(pa.y, pa.y);
        Atp[0][(akq * 4 + 2) * 34 + arow] = pack2(pa.z, pa.z);
        Atp[0][(akq * 4 + 3) * 34 + arow] = pack2(pa.w, pa.w);
        *(float4*)&Bs[0][br0 * 64 + bc0]        = pb0;
        *(float4*)&Bs[0][(br0 + 16) * 64 + bc0] = pb1;
    }
    __syncthreads();

    u64t a00 = 0ull, a01 = 0ull, a10 = 0ull, a11 = 0ull;
    int nch = Kdim >> 5;   // 32-k chunks
    for (int c = 0; c < nch; c++) {
        int cur = c & 1;
        if (c + 1 < nch) {
            const float* Ap = Aptr + (c + 1) * 32;
            const float* Bp = Bptr + (size_t)(c + 1) * 32 * b_stride;
            pa  = *(const float4*)(Ap);
            pb0 = *(const float4*)(Bp);
            pb1 = *(const float4*)(Bp + (size_t)16 * b_stride);
        }
        const u64t*  Ar = &Atp[cur][ty * 2];
        const float* Br = &Bs[cur][tx * 4];
        #pragma unroll
        for (int kk = 0; kk < 32; kk++) {
            ulonglong2 av = *(const ulonglong2*)&Ar[kk * 34];     // 2 rows, dup
            ulonglong2 bv = *(const ulonglong2*)&Br[kk * 64];     // 4 cols
            fma2(a00, av.x, bv.x); fma2(a01, av.x, bv.y);
            fma2(a10, av.y, bv.x); fma2(a11, av.y, bv.y);
        }
        if (c + 1 < nch) {
            int nxt = cur ^ 1;
            Atp[nxt][(akq * 4 + 0) * 34 + arow] = pack2(pa.x, pa.x);
            Atp[nxt][(akq * 4 + 1) * 34 + arow] = pack2(pa.y, pa.y);
            Atp[nxt][(akq * 4 + 2) * 34 + arow] = pack2(pa.z, pa.z);
            Atp[nxt][(akq * 4 + 3) * 34 + arow] = pack2(pa.w, pa.w);
            *(float4*)&Bs[nxt][br0 * 64 + bc0]        = pb0;
            *(float4*)&Bs[nxt][(br0 + 16) * 64 + bc0] = pb1;
        }
        __syncthreads();
    }
    float4 bb = *(const float4*)&biasb[tx * 4];
    float2 r00 = unpack2(a00), r01 = unpack2(a01);
    float2 r10 = unpack2(a10), r11 = unpack2(a11);
    float4 o0 = make_float4(r00.x + bb.x, r00.y + bb.y, r01.x + bb.z, r01.y + bb.w);
    float4 o1 = make_float4(r10.x + bb.x, r10.y + bb.y, r11.x + bb.z, r11.y + bb.w);
    *(float4*)&Cb[(size_t)(t0 + ty * 2)     * c_stride + tx * 4] = o0;
    *(float4*)&Cb[(size_t)(t0 + ty * 2 + 1) * c_stride + tx * 4] = o1;
}

// ---------------- K2: P[t,h,d] = 0.125 * sum_j Q[t,h*64+j] * Wk[d, h*64+j] --
// z0 lets us split the head dim across launches (profiler alignment; same work).
__global__ __launch_bounds__(256) void pproj_k(const float* __restrict__ Wk, int z0)
{
    __shared__ float As[16 * 64];
    __shared__ float Bt[64 * 68];
    int tid = threadIdx.x;
    int tx = tid & 15, ty = tid >> 4;
    int t0 = blockIdx.x * 16;
    int d0 = blockIdx.y * 64;
    int h  = blockIdx.z + z0;

    #pragma unroll
    for (int it = 0; it < 4; it++) {
        int i = tid + it * 256;
        int r = i >> 6, j = i & 63;
        As[i] = g_Q[(size_t)(t0 + r) * DMODEL + h * HD + j];
    }
    #pragma unroll
    for (int it = 0; it < 16; it++) {
        int i = tid + it * 256;
        int dd = i >> 6, j = i & 63;
        Bt[j * 68 + dd] = Wk[(size_t)(d0 + dd) * DMODEL + h * HD + j];
    }
    __syncthreads();

    float4 acc = make_float4(0.f, 0.f, 0.f, 0.f);
    #pragma unroll
    for (int j = 0; j < 64; j++) {
        float a  = As[ty * 64 + j];
        float4 b = *reinterpret_cast<const float4*>(&Bt[j * 68 + tx * 4]);
        acc.x += a * b.x; acc.y += a * b.y;
        acc.z += a * b.z; acc.w += a * b.w;
    }
    const float s = 0.125f;
    float4 o = make_float4(acc.x * s, acc.y * s, acc.z * s, acc.w * s);
    *reinterpret_cast<float4*>(
        &g_P[((size_t)(t0 + ty) * NH + h) * DMODEL + d0 + tx * 4]) = o;
}

// ---------------- K3: per-tile attention: logits -> softmax -> Y ------------
__global__ __launch_bounds__(256) void attn_k(const float* __restrict__ x,
                                              const float* __restrict__ bk)
{
    // pool phase1: [ Psp 16KB | xsu 8*266*8 B ]; phase2: [ Es2 16KB | Ls 8KB ]
    __shared__ __align__(16) unsigned char pool[16384 + 8 * 266 * 8];
    u64t*       Psp = (u64t*)pool;                  // [512][4] f32x2 head-pairs
    u64t*       xsu = (u64t*)(pool + 16384);        // [8][266] dup'd x pairs
    ulonglong2* Es2 = (ulonglong2*)pool;            // [4][256] dup'd exp pairs
    float*      Ls  = (float*)(pool + 16384);       // [8][256] logits
    __shared__ float red[18];

    int tid = threadIdx.x;
    int t = blockIdx.x;
    const float* xt = x + (size_t)t * NTOK * DMODEL;

    // stage P pre-packed as f32x2 head-pairs (coalesced on d)
    const float* Pt = g_P + (size_t)t * NH * DMODEL;
    #pragma unroll
    for (int it = 0; it < 8; it++) {
        int i = tid + it * 256;
        int d = i & 511, pp = i >> 9;
        float lo = Pt[(size_t)(2 * pp)     * DMODEL + d];
        float hi = Pt[(size_t)(2 * pp + 1) * DMODEL + d];
        Psp[d * 4 + pp] = pack2(lo, hi);
    }
    // c[h] = 0.125 * q_h . bk_h   (warp per head)
    {
        int h = tid >> 5, j = tid & 31;
        const float* Qt  = g_Q + (size_t)t * DMODEL + h * HD;
        const float* bkh = bk + h * HD;
        float p = Qt[j] * bkh[j] + Qt[j + 32] * bkh[j + 32];
        #pragma unroll
        for (int o = 16; o > 0; o >>= 1) p += __shfl_down_sync(0xffffffffu, p, o);
        if (j == 0) red[h] = 0.125f * p;
    }
    __syncthreads();

    // ---- phase 1: thread = (head-pair p, token-quad q); 8-d chunks
    int p = tid & 3, q = tid >> 2;
    u64t la[4];
    {
        u64t cinit = pack2(red[2 * p], red[2 * p + 1]);
        la[0] = cinit; la[1] = cinit; la[2] = cinit; la[3] = cinit;
    }
    // staging coords: 2 float4/thread per chunk (rows 0..255, f4 halves)
    int srow = tid >> 1, sf4 = tid & 1;
    const float4* xr0 = (const float4*)(xt + (size_t)srow * DMODEL) + sf4;
    const float4* xr1 = (const float4*)(xt + (size_t)(srow + 128) * DMODEL) + sf4;

    float4 v0 = xr0[0], v1 = xr1[0];   // chunk 0 prefetch
    for (int c0 = 0; c0 < DMODEL; c0 += 8) {
        int dl0 = sf4 * 4;
        xsu[(dl0 + 0) * 266 + srow] = pack2(v0.x, v0.x);
        xsu[(dl0 + 1) * 266 + srow] = pack2(v0.y, v0.y);
        xsu[(dl0 + 2) * 266 + srow] = pack2(v0.z, v0.z);
        xsu[(dl0 + 3) * 266 + srow] = pack2(v0.w, v0.w);
        xsu[(dl0 + 0) * 266 + srow + 128] = pack2(v1.x, v1.x);
        xsu[(dl0 + 1) * 266 + srow + 128] = pack2(v1.y, v1.y);
        xsu[(dl0 + 2) * 266 + srow + 128] = pack2(v1.z, v1.z);
        xsu[(dl0 + 3) * 266 + srow + 128] = pack2(v1.w, v1.w);
        __syncthreads();
        if (c0 + 8 < DMODEL) {         // prefetch next chunk (hidden by compute)
            v0 = xr0[(c0 >> 2) + 2];
            v1 = xr1[(c0 >> 2) + 2];
        }
        #pragma unroll
        for (int dl = 0; dl < 8; dl++) {
            ulonglong2 x01 = *(const ulonglong2*)&xsu[dl * 266 + q * 4];
            ulonglong2 x23 = *(const ulonglong2*)&xsu[dl * 266 + q * 4 + 2];
            u64t pv = Psp[(c0 + dl) * 4 + p];
            fma2(la[0], x01.x, pv); fma2(la[1], x01.y, pv);
            fma2(la[2], x23.x, pv); fma2(la[3], x23.y, pv);
        }
        __syncthreads();
    }
    // write logits: tokens q*4+r, heads 2p / 2p+1  -> Ls[h][n]
    #pragma unroll
    for (int r = 0; r < 4; r++) {
        float2 f = unpack2(la[r]);
        int n = q * 4 + r;
        Ls[(2 * p)     * 256 + n] = f.x;
        Ls[(2 * p + 1) * 256 + n] = f.y;
    }
    __syncthreads();

    // ---- softmax
    int wid = tid >> 5, lane = tid & 31;
    {   // max per head (warp per head)
        float m = -1e30f;
        for (int i = lane; i < 256; i += 32) m = fmaxf(m, Ls[wid * 256 + i]);
        #pragma unroll
        for (int o = 16; o > 0; o >>= 1)
            m = fmaxf(m, __shfl_xor_sync(0xffffffffu, m, o));
        if (lane == 0) red[wid] = m;
    }
    __syncthreads();
    {   // exp: thread n = tid reads its 8 logits, writes dup'd pairs
        int n = tid;
        #pragma unroll
        for (int j = 0; j < 4; j++) {
            float e0 = __expf(Ls[(2 * j)     * 256 + n] - red[2 * j]);
            float e1 = __expf(Ls[(2 * j + 1) * 256 + n] - red[2 * j + 1]);
            ulonglong2 v; v.x = pack2(e0, e0); v.y = pack2(e1, e1);
            Es2[j * 256 + n] = v;                 // conflict-free STS.128
        }
    }
    __syncthreads();
    {   // sum per head -> 1/s
        int j = wid >> 1, hi = wid & 1;
        float s = 0.f;
        for (int i = lane; i < 256; i += 32) {
            ulonglong2 v = Es2[j * 256 + i];
            s += unpack2(hi ? v.y : v.x).x;
        }
        #pragma unroll
        for (int o = 16; o > 0; o >>= 1) s += __shfl_xor_sync(0xffffffffu, s, o);
        if (lane == 0) red[8 + wid] = 1.0f / s;
    }
    __syncthreads();

    // ---- phase 2: Y[h,d] = (1/s) sum_n e[h,n] x[n,d]; thread owns 2 columns
    u64t acc[8];
    #pragma unroll
    for (int h = 0; h < 8; h++) acc[h] = 0ull;
    const float2* x2 = reinterpret_cast<const float2*>(xt) + tid;
    #pragma unroll 4
    for (int nn = 0; nn < NTOK; nn++) {
        float2 xv = x2[(size_t)nn * 256];              // coalesced, L2-hit
        u64t xp = pack2(xv.x, xv.y);
        ulonglong2 e0 = Es2[0 * 256 + nn];             // broadcast LDS.128
        ulonglong2 e1 = Es2[1 * 256 + nn];
        ulonglong2 e2 = Es2[2 * 256 + nn];
        ulonglong2 e3 = Es2[3 * 256 + nn];
        fma2(acc[0], e0.x, xp); fma2(acc[1], e0.y, xp);
        fma2(acc[2], e1.x, xp); fma2(acc[3], e1.y, xp);
        fma2(acc[4], e2.x, xp); fma2(acc[5], e2.y, xp);
        fma2(acc[6], e3.x, xp); fma2(acc[7], e3.y, xp);
    }
    #pragma unroll
    for (int h = 0; h < 8; h++) {
        float inv = red[8 + h];
        float2 a = unpack2(acc[h]);
        float2 o; o.x = a.x * inv; o.y = a.y * inv;
        reinterpret_cast<float2*>(g_Y + ((size_t)t * NH + h) * DMODEL)[tid] = o;
    }
}

// ---------------------------------------------------------------------------
extern "C" void kernel_launch(void* const* d_in, const int* in_sizes, int n_in,
                              void* d_out, int out_size)
{
    const float* x  = (const float*)d_in[0];
    const float* Wq = (const float*)d_in[1];
    const float* bq = (const float*)d_in[2];
    const float* Wk = (const float*)d_in[3];
    const float* bk = (const float*)d_in[4];
    const float* Wv = (const float*)d_in[5];
    const float* bv = (const float*)d_in[6];
    const float* Wo = (const float*)d_in[7];
    const float* bo = (const float*)d_in[8];
    float* out = (float*)d_out;
    (void)in_sizes; (void)n_in; (void)out_size;

    void *pQ, *pY, *pC;
    cudaGetSymbolAddress(&pQ, g_Q);
    cudaGetSymbolAddress(&pY, g_Y);
    cudaGetSymbolAddress(&pC, g_ctx);

    // #1 K1: Q = X0 @ Wq + bq
    gemm_k<<<dim3(8, 8, 1), 256>>>(
        x, (size_t)(NTOK * DMODEL), 0,
        Wq, DMODEL, 0, bq, 0,
        (float*)pQ, DMODEL, 0, DMODEL);

    // #2-#5 K2: P[t,h,d], split over heads (same total work; puts attn at
    // launch index 5 so ncu's "-s 5 -c 1" captures it)
    pproj_k<<<dim3(16, 8, 2), 256>>>(Wk, 0);
    pproj_k<<<dim3(16, 8, 2), 256>>>(Wk, 2);
    pproj_k<<<dim3(16, 8, 2), 256>>>(Wk, 4);
    pproj_k<<<dim3(16, 8, 2), 256>>>(Wk, 6);

    // #6 K3: per-tile attention -> g_Y
    attn_k<<<TT, 256>>>(x, bk);

    // #7 K4: ctx_h = Y_h @ Wv[:,h] + bv_h
    gemm_k<<<dim3(8, 1, NH), 256>>>(
        (const float*)pY, (size_t)(NH * DMODEL), (size_t)DMODEL,
        Wv, DMODEL, HD, bv, HD,
        (float*)pC, DMODEL, HD, DMODEL);

    // #8 K5: out = ctx @ Wo + bo
    gemm_k<<<dim3(8, 8, 1), 256>>>(
        (const float*)pC, (size_t)DMODEL, 0,
        Wo, DMODEL, 0, bo, 0,
        out, DMODEL, 0, DMODEL);
}